// round 12
// baseline (speedup 1.0000x reference)
#include <cuda_runtime.h>
#include <cuda_bf16.h>

#define DIM   128
#define ROWV  32              // float4 per row
#define NTYP_MAX 4096
#define FUSED_GRID 592        // 4 CTAs/SM * 148 SMs -> all resident (barrier-safe)

// Precomputed group-sum table: S[j] = sum_{k=0..3} out[lcom[(j+k)%n_typ]]
__device__ float4 g_S[NTYP_MAX * ROWV];

// Monotonic barrier counter — NEVER reset -> graph-replay safe.
__device__ unsigned g_bar;

// ---------------------------------------------------------------------------
// Fused kernel: phase 1 = sub2 (grid-stride over type nodes), grid barrier,
// phase 2 = build_S. One launch. (Unchanged from R10 — it works.)
// ---------------------------------------------------------------------------
__global__ __launch_bounds__(256, 4)
void sub2_buildS_fused(const float4* __restrict__ emb4,
                       const int4*   __restrict__ s2row4,
                       const int*    __restrict__ lspec,
                       const int*    __restrict__ rcom,
                       const int*    __restrict__ lcom,
                       float4*       __restrict__ out4,
                       float addc, int n_typ)
{
    __shared__ float4 part[8][ROWV];

    const int lane = threadIdx.x & 31;
    const int g    = threadIdx.x >> 5;

    for (int c = blockIdx.x; c < n_typ; c += gridDim.x) {
        const int4 ea = __ldg(&s2row4[c * 16 + g * 2]);
        const int4 eb = __ldg(&s2row4[c * 16 + g * 2 + 1]);

        const int s0 = __ldg(&lspec[ea.x]);
        const int s1 = __ldg(&lspec[ea.y]);
        const int s2 = __ldg(&lspec[ea.z]);
        const int s3 = __ldg(&lspec[ea.w]);
        const int s4 = __ldg(&lspec[eb.x]);
        const int s5 = __ldg(&lspec[eb.y]);
        const int s6 = __ldg(&lspec[eb.z]);
        const int s7 = __ldg(&lspec[eb.w]);

        float4 v0 = __ldcs(&emb4[s0 * ROWV + lane]);
        float4 v1 = __ldcs(&emb4[s1 * ROWV + lane]);
        float4 v2 = __ldcs(&emb4[s2 * ROWV + lane]);
        float4 v3 = __ldcs(&emb4[s3 * ROWV + lane]);
        float4 v4 = __ldcs(&emb4[s4 * ROWV + lane]);
        float4 v5 = __ldcs(&emb4[s5 * ROWV + lane]);
        float4 v6 = __ldcs(&emb4[s6 * ROWV + lane]);
        float4 v7 = __ldcs(&emb4[s7 * ROWV + lane]);

        float4 a;
        a.x = ((v0.x + v1.x) + (v2.x + v3.x)) + ((v4.x + v5.x) + (v6.x + v7.x));
        a.y = ((v0.y + v1.y) + (v2.y + v3.y)) + ((v4.y + v5.y) + (v6.y + v7.y));
        a.z = ((v0.z + v1.z) + (v2.z + v3.z)) + ((v4.z + v5.z) + (v6.z + v7.z));
        a.w = ((v0.w + v1.w) + (v2.w + v3.w)) + ((v4.w + v5.w) + (v6.w + v7.w));
        part[g][lane] = a;
        __syncthreads();

        if (g == 0) {
            const int tgt = __ldg(&rcom[c]);
            float4 p0 = part[0][lane], p1 = part[1][lane];
            float4 p2 = part[2][lane], p3 = part[3][lane];
            float4 p4 = part[4][lane], p5 = part[5][lane];
            float4 p6 = part[6][lane], p7 = part[7][lane];
            float4 base = __ldg(&emb4[tgt * ROWV + lane]);
            float4 r;
            r.x = base.x + ((p0.x + p1.x) + (p2.x + p3.x))
                         + ((p4.x + p5.x) + (p6.x + p7.x)) + addc;
            r.y = base.y + ((p0.y + p1.y) + (p2.y + p3.y))
                         + ((p4.y + p5.y) + (p6.y + p7.y)) + addc;
            r.z = base.z + ((p0.z + p1.z) + (p2.z + p3.z))
                         + ((p4.z + p5.z) + (p6.z + p7.z)) + addc;
            r.w = base.w + ((p0.w + p1.w) + (p2.w + p3.w))
                         + ((p4.w + p5.w) + (p6.w + p7.w)) + addc;
            out4[tgt * ROWV + lane] = r;
        }
        __syncthreads();
    }

    // grid barrier (all CTAs resident via __launch_bounds__(256,4))
    __syncthreads();
    if (threadIdx.x == 0) {
        __threadfence();
        unsigned t = atomicAdd(&g_bar, 1u) + 1u;
        unsigned target = ((t + gridDim.x - 1u) / gridDim.x) * gridDim.x;
        while (*(volatile unsigned*)&g_bar < target) { }
        __threadfence();
    }
    __syncthreads();

    // phase 2: build S (reads of out4 via L2-coherent __ldcg)
    const int total  = n_typ * ROWV;
    const int stride = gridDim.x * blockDim.x;
    for (int i = blockIdx.x * blockDim.x + threadIdx.x; i < total; i += stride) {
        const int j  = i >> 5;
        const int ln = i & 31;
        int j1 = j + 1; if (j1 >= n_typ) j1 -= n_typ;
        int j2 = j + 2; if (j2 >= n_typ) j2 -= n_typ;
        int j3 = j + 3; if (j3 >= n_typ) j3 -= n_typ;
        const int t0 = __ldg(&lcom[j]);
        const int t1 = __ldg(&lcom[j1]);
        const int t2 = __ldg(&lcom[j2]);
        const int t3 = __ldg(&lcom[j3]);
        float4 v0 = __ldcg(&out4[t0 * ROWV + ln]);
        float4 v1 = __ldcg(&out4[t1 * ROWV + ln]);
        float4 v2 = __ldcg(&out4[t2 * ROWV + ln]);
        float4 v3 = __ldcg(&out4[t3 * ROWV + ln]);
        float4 s;
        s.x = (v0.x + v1.x) + (v2.x + v3.x);
        s.y = (v0.y + v1.y) + (v2.y + v3.y);
        s.z = (v0.z + v1.z) + (v2.z + v3.z);
        s.w = (v0.w + v1.w) + (v2.w + v3.w);
        g_S[i] = s;
    }
}

// ---------------------------------------------------------------------------
// sub3 (deg3==4): one warp per FOUR entity rows. All loads batched for max
// MLP (~12 outstanding per warp). Warp-uniform consecutive-pattern check ->
// single S gather per entity; 4-gather fallback. 32-bit indexing throughout.
// ---------------------------------------------------------------------------
__global__ __launch_bounds__(256)
void sub3_kernel(const float4* __restrict__ emb4,
                 const int4*   __restrict__ edges4,
                 const int*    __restrict__ lcom,
                 const int*    __restrict__ rspec,
                 float4*       __restrict__ out4,
                 int n_ent, int n_typ, float add, float inv_sum)
{
    const int warp = threadIdx.x >> 5;
    const int lane = threadIdx.x & 31;
    const int base = (blockIdx.x * (blockDim.x >> 5) + warp) * 4;
    if (base >= n_ent) return;
    const int cnt = min(4, n_ent - base);

    int4   e[4];
    int    r[4];
    float4 iv[4];
    float4 a[4];

    // --- batched index loads ---
    #pragma unroll
    for (int k = 0; k < 4; ++k) {
        const int ent = (k < cnt) ? base + k : base;
        e[k] = __ldg(&edges4[ent]);
        r[k] = __ldg(&rspec[ent]);
    }
    // --- batched streaming entity reads ---
    #pragma unroll
    for (int k = 0; k < 4; ++k)
        iv[k] = __ldcs(&emb4[r[k] * ROWV + lane]);

    // --- gathers (warp-uniform branch per entity) ---
    #pragma unroll
    for (int k = 0; k < 4; ++k) {
        const int d1 = e[k].y - e[k].x, d2 = e[k].z - e[k].x, d3 = e[k].w - e[k].x;
        const bool ok = (d1 == 1 || d1 == 1 - n_typ)
                     && (d2 == 2 || d2 == 2 - n_typ)
                     && (d3 == 3 || d3 == 3 - n_typ);
        if (ok) {
            a[k] = __ldg(&g_S[e[k].x * ROWV + lane]);
        } else {
            const int t0 = __ldg(&lcom[e[k].x]), t1 = __ldg(&lcom[e[k].y]);
            const int t2 = __ldg(&lcom[e[k].z]), t3 = __ldg(&lcom[e[k].w]);
            float4 g0 = __ldg(&out4[t0 * ROWV + lane]);
            float4 g1 = __ldg(&out4[t1 * ROWV + lane]);
            float4 g2 = __ldg(&out4[t2 * ROWV + lane]);
            float4 g3 = __ldg(&out4[t3 * ROWV + lane]);
            a[k].x = (g0.x + g1.x) + (g2.x + g3.x);
            a[k].y = (g0.y + g1.y) + (g2.y + g3.y);
            a[k].z = (g0.z + g1.z) + (g2.z + g3.z);
            a[k].w = (g0.w + g1.w) + (g2.w + g3.w);
        }
    }

    // --- compute + streaming stores ---
    #pragma unroll
    for (int k = 0; k < 4; ++k) {
        if (k < cnt) {
            float4 w;
            w.x = iv[k].x * (1.0f - (a[k].x + add) * inv_sum);
            w.y = iv[k].y * (1.0f - (a[k].y + add) * inv_sum);
            w.z = iv[k].z * (1.0f - (a[k].z + add) * inv_sum);
            w.w = iv[k].w * (1.0f - (a[k].w + add) * inv_sum);
            __stcs(&out4[r[k] * ROWV + lane], w);
        }
    }
}

// ---------------------------------------------------------------------------
// Fallback kernels (generic shapes).
// ---------------------------------------------------------------------------
__global__ __launch_bounds__(512)
void sub2_kernel_gen(const float* __restrict__ emb,
                     const int*   __restrict__ s2row,
                     const int*   __restrict__ lspec,
                     const int*   __restrict__ rcom,
                     float*       __restrict__ out,
                     float addc, int deg2)
{
    __shared__ float part[4][DIM];
    const int c = blockIdx.x;
    const int d = threadIdx.x & (DIM - 1);
    const int g = threadIdx.x >> 7;
    const int* __restrict__ e = s2row + (size_t)c * deg2;
    const int chunk = deg2 >> 2;
    const int j0 = g * chunk;
    const int j1 = (g == 3) ? deg2 : j0 + chunk;
    float acc = 0.0f;
    #pragma unroll 8
    for (int j = j0; j < j1; ++j) {
        int src = __ldg(&lspec[__ldg(&e[j])]);
        acc += __ldcs(&emb[(size_t)src * DIM + d]);
    }
    part[g][d] = acc;
    __syncthreads();
    if (g == 0) {
        const int tgt = rcom[c];
        float v = __ldg(&emb[(size_t)tgt * DIM + d])
                + part[0][d] + part[1][d] + part[2][d] + part[3][d] + addc;
        out[(size_t)tgt * DIM + d] = v;
    }
}

__global__ __launch_bounds__(256)
void build_S_kernel(const float4* __restrict__ out4,
                    const int*    __restrict__ lcom,
                    int n_typ)
{
    const int i = blockIdx.x * blockDim.x + threadIdx.x;
    if (i >= n_typ * ROWV) return;
    const int j    = i >> 5;
    const int lane = i & 31;
    int j1 = j + 1; if (j1 >= n_typ) j1 -= n_typ;
    int j2 = j + 2; if (j2 >= n_typ) j2 -= n_typ;
    int j3 = j + 3; if (j3 >= n_typ) j3 -= n_typ;
    const int t0 = __ldg(&lcom[j]);
    const int t1 = __ldg(&lcom[j1]);
    const int t2 = __ldg(&lcom[j2]);
    const int t3 = __ldg(&lcom[j3]);
    float4 v0 = __ldg(&out4[t0 * ROWV + lane]);
    float4 v1 = __ldg(&out4[t1 * ROWV + lane]);
    float4 v2 = __ldg(&out4[t2 * ROWV + lane]);
    float4 v3 = __ldg(&out4[t3 * ROWV + lane]);
    float4 s;
    s.x = (v0.x + v1.x) + (v2.x + v3.x);
    s.y = (v0.y + v1.y) + (v2.y + v3.y);
    s.z = (v0.z + v1.z) + (v2.z + v3.z);
    s.w = (v0.w + v1.w) + (v2.w + v3.w);
    g_S[i] = s;
}

__global__ __launch_bounds__(256)
void sub3_kernel_gen(const float* __restrict__ emb,
                     const int*   __restrict__ s3row,
                     const int*   __restrict__ lcom,
                     const int*   __restrict__ rspec,
                     float*       __restrict__ out,
                     int n_ent, float n_typ_f, int deg3)
{
    const int warp = threadIdx.x >> 5;
    const int lane = threadIdx.x & 31;
    const int n = blockIdx.x * (blockDim.x >> 5) + warp;
    if (n >= n_ent) return;

    const float4* __restrict__ out4 = (const float4*)out;
    const int* __restrict__ e = s3row + (size_t)n * deg3;

    float4 acc = make_float4(0.f, 0.f, 0.f, 0.f);
    for (int j = 0; j < deg3; ++j) {
        int t = __ldg(&lcom[__ldg(&e[j])]);
        float4 v = __ldg(&out4[(size_t)t * ROWV + lane]);
        acc.x += v.x; acc.y += v.y; acc.z += v.z; acc.w += v.w;
    }
    const float add     = n_typ_f - (float)deg3;
    const float inv_sum = 1.0f / (1.0f + (float)deg3);
    const int   tgt     = rspec[n];
    float4 iv = __ldcs(&((const float4*)emb)[(size_t)tgt * ROWV + lane]);
    float4 r;
    r.x = iv.x * (1.0f - (acc.x + add) * inv_sum);
    r.y = iv.y * (1.0f - (acc.y + add) * inv_sum);
    r.z = iv.z * (1.0f - (acc.z + add) * inv_sum);
    r.w = iv.w * (1.0f - (acc.w + add) * inv_sum);
    __stcs(&((float4*)out)[(size_t)tgt * ROWV + lane], r);
}

// ---------------------------------------------------------------------------
// Launch. Inputs (metadata order):
//  0 all_node_embedding f32 | 1 sub2_row | 2 sub2_col | 3 sub3_row | 4 sub3_col
//  5 left_specific | 6 right_common | 7 left_common | 8 right_specific
// ---------------------------------------------------------------------------
extern "C" void kernel_launch(void* const* d_in, const int* in_sizes, int n_in,
                              void* d_out, int out_size)
{
    const float* emb   = (const float*)d_in[0];
    const int*   s2row = (const int*)  d_in[1];
    const int*   s3row = (const int*)  d_in[3];
    const int*   lspec = (const int*)  d_in[5];
    const int*   rcom  = (const int*)  d_in[6];
    const int*   lcom  = (const int*)  d_in[7];
    const int*   rspec = (const int*)  d_in[8];
    float*       out   = (float*)d_out;

    const int n_ent = in_sizes[5];
    const int n_typ = in_sizes[6];
    const int deg2  = in_sizes[1] / n_typ;
    const int deg3  = in_sizes[3] / in_sizes[8];

    if (deg2 == 64 && deg3 == 4 && n_typ <= NTYP_MAX) {
        // ---- fused sub2 + barrier + build_S (one launch) ----
        sub2_buildS_fused<<<FUSED_GRID, 256>>>(
            (const float4*)emb, (const int4*)s2row, lspec, rcom, lcom,
            (float4*)out, (float)n_ent - (float)deg2, n_typ);

        // ---- sub3: 4 entities per warp ----
        const int warps_per_block = 8;
        const int ents_per_block  = warps_per_block * 4;
        const int blocks = (n_ent + ents_per_block - 1) / ents_per_block;
        sub3_kernel<<<blocks, warps_per_block * 32>>>(
            (const float4*)emb, (const int4*)s3row, lcom, rspec,
            (float4*)out, n_ent, n_typ,
            (float)n_typ - 4.0f, 1.0f / 5.0f);
    } else {
        // ---- generic fallback path ----
        sub2_kernel_gen<<<n_typ, 512>>>(emb, s2row, lspec, rcom, out,
                                        (float)n_ent - (float)deg2, deg2);
        if (deg3 == 4 && n_typ <= NTYP_MAX) {
            const int s_threads = 256;
            const int s_blocks  = (n_typ * ROWV + s_threads - 1) / s_threads;
            build_S_kernel<<<s_blocks, s_threads>>>((const float4*)out, lcom, n_typ);
            // generic-shape sub3 via the per-entity fallback kernel
            const int warps_per_block = 8;
            const int blocks = (n_ent + warps_per_block - 1) / warps_per_block;
            sub3_kernel_gen<<<blocks, warps_per_block * 32>>>(
                emb, s3row, lcom, rspec, out, n_ent, (float)n_typ, deg3);
        } else {
            const int warps_per_block = 8;
            const int blocks = (n_ent + warps_per_block - 1) / warps_per_block;
            sub3_kernel_gen<<<blocks, warps_per_block * 32>>>(
                emb, s3row, lcom, rspec, out, n_ent, (float)n_typ, deg3);
        }
    }
}